// round 1
// baseline (speedup 1.0000x reference)
#include <cuda_runtime.h>

#define B_TOTAL 2048
#define NPTS    256
#define BIGV    66049.0f   // 257^2

__device__ float g_partial[B_TOTAL];

// One warp per batch. blockDim = 32, grid = 2048.
__global__ __launch_bounds__(32) void match_kernel(const float* __restrict__ inp,
                                                   const float* __restrict__ tgt) {
    const int lane = threadIdx.x & 31;
    const int b = blockIdx.x;

    __shared__ float s_tgt[2 * NPTS];

    // Stage targets for this batch into SMEM (coalesced float4).
    const float4* tg4 = (const float4*)(tgt + (size_t)b * 2 * NPTS);
    float4* st4 = (float4*)s_tgt;
    #pragma unroll
    for (int i = 0; i < 4; i++) st4[lane + 32 * i] = tg4[lane + 32 * i];

    // Each lane owns 8 input points: k = lane + 32*i (coalesced float2 loads).
    float px[8], py[8], bias[8];
    const float2* in2 = (const float2*)(inp + (size_t)b * 2 * NPTS);
    #pragma unroll
    for (int i = 0; i < 8; i++) {
        float2 p = in2[lane + 32 * i];
        px[i] = p.x;
        py[i] = p.y;
        bias[i] = 0.0f;   // becomes 1e30f once point is used
    }
    __syncwarp();

    const float2* st2 = (const float2*)s_tgt;
    float acc = 0.0f;

    for (int j = 0; j < NPTS; j++) {
        float2 t2 = st2[j];             // broadcast LDS, conflict-free

        // Local strict-< argmin over this lane's 8 points.
        float dmin = __int_as_float(0x7f800000);  // +inf
        int   kmin = 0;
        #pragma unroll
        for (int i = 0; i < 8; i++) {
            float dx = t2.x - px[i];
            float dy = t2.y - py[i];
            float d  = dx * dx + dy * dy + bias[i];
            if (d < dmin) { dmin = d; kmin = lane + 32 * i; }
        }

        // Pack (dist, index): positive-float bits are monotone as unsigned,
        // so u64-min == exact dist compare with lowest-k tie-break (matches
        // jnp.argmin first-min semantics).
        unsigned long long key =
            ((unsigned long long)__float_as_uint(dmin) << 32) | (unsigned)kmin;

        #pragma unroll
        for (int off = 16; off; off >>= 1) {
            unsigned long long o = __shfl_xor_sync(0xffffffffu, key, off);
            key = (o < key) ? o : key;
        }

        float m    = __uint_as_float((unsigned)(key >> 32));
        int   kwin = (int)(key & 0xffffffffu);

        acc += fminf(m, BIGV);                 // se = min(m, BIG)
        int kk = (m < BIGV) ? kwin : 0;        // k stays 0 if nothing beats BIG

        // Mark winner used (bias -> 1e30). Unrolled to keep bias[] in regs.
        if ((kk & 31) == lane) {
            int slot = kk >> 5;
            #pragma unroll
            for (int i = 0; i < 8; i++)
                if (slot == i) bias[i] = 1e30f;
        }
    }

    if (lane == 0) g_partial[b] = acc;
}

// Deterministic fixed-order reduction of the 2048 per-batch partial sums.
__global__ void reduce_kernel(float* __restrict__ out) {
    __shared__ double s[256];
    int t = threadIdx.x;
    double a = 0.0;
    #pragma unroll
    for (int i = 0; i < B_TOTAL / 256; i++)
        a += (double)g_partial[t + 256 * i];
    s[t] = a;
    __syncthreads();
    for (int stride = 128; stride > 0; stride >>= 1) {
        if (t < stride) s[t] += s[t + stride];
        __syncthreads();
    }
    if (t == 0)
        out[0] = (float)(s[0] / (double)B_TOTAL / (double)(2 * NPTS));
}

extern "C" void kernel_launch(void* const* d_in, const int* in_sizes, int n_in,
                              void* d_out, int out_size) {
    const float* inp = (const float*)d_in[0];   // "input"
    const float* tgt = (const float*)d_in[1];   // "targets"
    float* out = (float*)d_out;

    match_kernel<<<B_TOTAL, 32>>>(inp, tgt);
    reduce_kernel<<<1, 256>>>(out);
}

// round 2
// speedup vs baseline: 1.4562x; 1.4562x over previous
#include <cuda_runtime.h>

#define B_TOTAL 2048
#define NPTS    256
#define BIGV    66049.0f   // 257^2

__device__ float g_partial[B_TOTAL];
__device__ int   g_ctr;    // zero-init; last block resets to 0 each run

// One warp per batch. blockDim = 32, grid = 2048.
__global__ __launch_bounds__(32) void match_kernel(const float* __restrict__ inp,
                                                   const float* __restrict__ tgt,
                                                   float* __restrict__ out) {
    const int lane = threadIdx.x;
    const int b = blockIdx.x;

    __shared__ float s_tgt[2 * NPTS];

    // Stage targets (coalesced float4).
    const float4* tg4 = (const float4*)(tgt + (size_t)b * 2 * NPTS);
    float4* st4 = (float4*)s_tgt;
    #pragma unroll
    for (int i = 0; i < 4; i++) st4[lane + 32 * i] = tg4[lane + 32 * i];

    // Each lane owns 8 input points: k = lane + 32*i.
    // c[i] = |p|^2, becomes 1e30 once used (bias folded into the constant).
    float px[8], py[8], c[8];
    const float2* in2 = (const float2*)(inp + (size_t)b * 2 * NPTS);
    #pragma unroll
    for (int i = 0; i < 8; i++) {
        float2 p = in2[lane + 32 * i];
        px[i] = p.x;
        py[i] = p.y;
        c[i]  = fmaf(p.x, p.x, p.y * p.y);
    }
    __syncwarp();

    const float2* st2 = (const float2*)s_tgt;
    float acc = 0.0f;

    #pragma unroll 4
    for (int j = 0; j < NPTS; j++) {
        float2 t = st2[j];                       // broadcast LDS
        float tx2 = -2.0f * t.x;
        float ty2 = -2.0f * t.y;
        float tt  = fmaf(t.x, t.x, t.y * t.y);

        // d_cmp[i] = |t-p|^2 - |t|^2  (ordering identical; 2 FMA per point)
        float d[8];
        #pragma unroll
        for (int i = 0; i < 8; i++)
            d[i] = fmaf(tx2, px[i], fmaf(ty2, py[i], c[i]));

        // Balanced pairwise argmin tree; strict '<' keeps lowest index on ties.
        float m01 = d[0]; int s01 = 0; if (d[1] < m01) { m01 = d[1]; s01 = 1; }
        float m23 = d[2]; int s23 = 2; if (d[3] < m23) { m23 = d[3]; s23 = 3; }
        float m45 = d[4]; int s45 = 4; if (d[5] < m45) { m45 = d[5]; s45 = 5; }
        float m67 = d[6]; int s67 = 6; if (d[7] < m67) { m67 = d[7]; s67 = 7; }
        float m03 = m01;  int s03 = s01; if (m23 < m03) { m03 = m23; s03 = s23; }
        float m47 = m45;  int s47 = s45; if (m67 < m47) { m47 = m67; s47 = s67; }
        float dmin = m03; int smin = s03; if (m47 < dmin) { dmin = m47; smin = s47; }

        // Sortable-uint transform (handles negative d_cmp), pack 8-bit k into
        // the low byte. Truncating 8 mantissa bits only collapses near-exact
        // ties (rel ~3e-5), which then break toward lowest k — matches ref
        // semantics to within tolerance.
        unsigned ub = __float_as_uint(dmin);
        unsigned us = ub ^ ((unsigned)(((int)ub) >> 31) | 0x80000000u);
        unsigned k  = (unsigned)(lane + (smin << 5));
        unsigned key = (us & 0xFFFFFF00u) | k;

        unsigned kw = __reduce_min_sync(0xFFFFFFFFu, key);   // one REDUX

        if (key == kw) {                 // exactly one winning lane
            acc += fminf(dmin + tt, BIGV);
            #pragma unroll
            for (int i = 0; i < 8; i++)
                if (smin == i) c[i] = 1e30f;   // mark used
        }
    }

    // Per-warp sum of per-lane partials.
    #pragma unroll
    for (int off = 16; off; off >>= 1)
        acc += __shfl_xor_sync(0xffffffffu, acc, off);

    if (lane == 0) g_partial[b] = acc;
    __threadfence();

    // Last-block-done: fused deterministic final reduction (fixed order, fp64).
    int last = 0;
    if (lane == 0) last = (atomicAdd(&g_ctr, 1) == B_TOTAL - 1);
    last = __shfl_sync(0xffffffffu, last, 0);
    if (last) {
        __threadfence();
        double s = 0.0;
        #pragma unroll
        for (int i = 0; i < B_TOTAL / 32; i++)
            s += (double)g_partial[lane + 32 * i];
        #pragma unroll
        for (int off = 16; off; off >>= 1)
            s += __shfl_xor_sync(0xffffffffu, s, off);
        if (lane == 0) {
            out[0] = (float)(s / (double)B_TOTAL / (double)(2 * NPTS));
            g_ctr = 0;                   // reset for next graph replay
        }
    }
}

extern "C" void kernel_launch(void* const* d_in, const int* in_sizes, int n_in,
                              void* d_out, int out_size) {
    const float* inp = (const float*)d_in[0];   // "input"
    const float* tgt = (const float*)d_in[1];   // "targets"
    match_kernel<<<B_TOTAL, 32>>>(inp, tgt, (float*)d_out);
}

// round 6
// speedup vs baseline: 2.0259x; 1.3913x over previous
#include <cuda_runtime.h>

#define B_TOTAL 2048
#define NPTS    256

__device__ float g_partial[B_TOTAL];
__device__ int   g_ctr;    // zero-init; last block resets it each run

// One warp per batch. blockDim = 32, grid = 2048.
// Point k = 8*lane + slot (k is the true input index -> tie-break matches ref).
__global__ __launch_bounds__(32) void match_kernel(const float* __restrict__ inp,
                                                   const float* __restrict__ tgt,
                                                   float* __restrict__ out) {
    const int lane = threadIdx.x;
    const int b = blockIdx.x;

    __shared__ float s_tgt[2 * NPTS];
    // Stride 10 floats (40 B) per lane: float2 accesses are 8B-aligned
    // (40*lane % 8 == 0) and the LDS.64 two-phase bank pattern
    // (10*lane mod 32 over 16 lanes) is conflict-free.
    __shared__ float s_c[10 * 32];

    // Stage targets (coalesced float4) and accumulate sum of |t|^2.
    const float4* tg4 = (const float4*)(tgt + (size_t)b * 2 * NPTS);
    float4* st4 = (float4*)s_tgt;
    float tts = 0.0f;
    #pragma unroll
    for (int i = 0; i < 4; i++) {
        float4 v = tg4[lane + 32 * i];
        st4[lane + 32 * i] = v;
        tts += fmaf(v.x, v.x, v.y * v.y) + fmaf(v.z, v.z, v.w * v.w);
    }

    // Own 8 consecutive points (coalesced float4): k = 8*lane + i.
    float px[8], py[8];
    const float4* in4 = (const float4*)(inp + (size_t)b * 2 * NPTS);
    #pragma unroll
    for (int p = 0; p < 4; p++) {
        float4 v = in4[4 * lane + p];
        px[2 * p]     = v.x;  py[2 * p]     = v.y;
        px[2 * p + 1] = v.z;  py[2 * p + 1] = v.w;
    }
    // c[i] = |p|^2 + 64  (+64 keeps d positive so uint-min == float-min);
    // becomes 1e30 once the point is used.
    #pragma unroll
    for (int i = 0; i < 8; i++)
        s_c[10 * lane + i] = fmaf(px[i], px[i], fmaf(py[i], py[i], 64.0f));

    unsigned kreg[8];
    #pragma unroll
    for (int i = 0; i < 8; i++) kreg[i] = 8u * (unsigned)lane + (unsigned)i;

    __syncwarp();

    const float2* st2 = (const float2*)s_tgt;
    float acc = 0.0f;   // uniform across lanes

    #pragma unroll 4
    for (int j = 0; j < NPTS; j++) {
        float2 t = st2[j];                       // broadcast LDS
        float tx2 = -2.0f * t.x;
        float ty2 = -2.0f * t.y;

        // d[i] = |t-p|^2 - |t|^2 + 64 > 0   (2 FMA per point, c from SMEM)
        float c[8];
        #pragma unroll
        for (int p = 0; p < 4; p++) {
            float2 cc = *(const float2*)&s_c[10 * lane + 2 * p];
            c[2 * p] = cc.x;  c[2 * p + 1] = cc.y;
        }
        unsigned key[8];
        #pragma unroll
        for (int i = 0; i < 8; i++) {
            float d = fmaf(tx2, px[i], fmaf(ty2, py[i], c[i]));
            key[i] = (__float_as_uint(d) & 0xFFFFFF00u) | kreg[i];
        }

        // Integer min tree (IMNMX) + one REDUX: value-order with lowest-k ties.
        unsigned m0 = min(key[0], key[1]);
        unsigned m1 = min(key[2], key[3]);
        unsigned m2 = min(key[4], key[5]);
        unsigned m3 = min(key[6], key[7]);
        unsigned lmin = min(min(m0, m1), min(m2, m3));
        unsigned kw = __reduce_min_sync(0xFFFFFFFFu, lmin);

        // Uniform accumulate: truncated d + half-quantum de-bias (2^(e-16)).
        float dec = __uint_as_float(kw & 0xFFFFFF00u);
        float hq  = __uint_as_float(kw & 0x7F800000u) * (1.0f / 65536.0f);
        acc += dec + hq;

        // Winner lane poisons its point: one predicated STS.
        unsigned kwin = kw & 0xFFu;
        if ((kwin >> 3) == (unsigned)lane)
            s_c[10 * lane + (kwin & 7u)] = 1e30f;
        __syncwarp();
    }

    // Sum of |t|^2 over the batch (warp butterfly, off critical path).
    #pragma unroll
    for (int off = 16; off; off >>= 1)
        tts += __shfl_xor_sync(0xffffffffu, tts, off);

    // se_j = d_j - 64 + |t_j|^2  =>  batch sum = acc + tts - 64*256
    if (lane == 0) g_partial[b] = acc + tts - 64.0f * NPTS;
    __threadfence();

    // Fused deterministic final reduction (last block, fixed order, fp64).
    int last = 0;
    if (lane == 0) last = (atomicAdd(&g_ctr, 1) == B_TOTAL - 1);
    last = __shfl_sync(0xffffffffu, last, 0);
    if (last) {
        __threadfence();
        double s = 0.0;
        #pragma unroll
        for (int i = 0; i < B_TOTAL / 32; i++)
            s += (double)g_partial[lane + 32 * i];
        #pragma unroll
        for (int off = 16; off; off >>= 1)
            s += __shfl_xor_sync(0xffffffffu, s, off);
        if (lane == 0) {
            out[0] = (float)(s / (double)B_TOTAL / (double)(2 * NPTS));
            g_ctr = 0;                  // reset for next graph replay
        }
    }
}

extern "C" void kernel_launch(void* const* d_in, const int* in_sizes, int n_in,
                              void* d_out, int out_size) {
    const float* inp = (const float*)d_in[0];   // "input"
    const float* tgt = (const float*)d_in[1];   // "targets"
    match_kernel<<<B_TOTAL, 32>>>(inp, tgt, (float*)d_out);
}

// round 7
// speedup vs baseline: 2.1090x; 1.0411x over previous
#include <cuda_runtime.h>

#define B_TOTAL 2048
#define NPTS    256

__device__ float g_partial[B_TOTAL];
__device__ int   g_ctr;    // zero-init; last block resets it each run

// One warp per batch. blockDim = 32, grid = 2048.
// Point k = 8*lane + slot (true input index -> tie-break matches ref).
// Processes TWO targets per iteration; a rare warp-uniform fallback handles
// the case where target j+1's argmin is the point target j just consumed.
__global__ __launch_bounds__(32) void match_kernel(const float* __restrict__ inp,
                                                   const float* __restrict__ tgt,
                                                   float* __restrict__ out) {
    const int lane = threadIdx.x;
    const int b = blockIdx.x;

    __shared__ float s_tgt[2 * NPTS];
    // Stride 10 floats (40 B) per lane: float2 accesses 8B-aligned, and the
    // LDS.64 two-phase bank pattern (10*lane mod 32 over 16 lanes) is
    // conflict-free.
    __shared__ float s_c[10 * 32];

    // Stage targets (coalesced float4) and accumulate sum of |t|^2.
    const float4* tg4 = (const float4*)(tgt + (size_t)b * 2 * NPTS);
    float4* st4 = (float4*)s_tgt;
    float tts = 0.0f;
    #pragma unroll
    for (int i = 0; i < 4; i++) {
        float4 v = tg4[lane + 32 * i];
        st4[lane + 32 * i] = v;
        tts += fmaf(v.x, v.x, v.y * v.y) + fmaf(v.z, v.z, v.w * v.w);
    }

    // Own 8 consecutive points (coalesced float4): k = 8*lane + i.
    float px[8], py[8];
    const float4* in4 = (const float4*)(inp + (size_t)b * 2 * NPTS);
    #pragma unroll
    for (int p = 0; p < 4; p++) {
        float4 v = in4[4 * lane + p];
        px[2 * p]     = v.x;  py[2 * p]     = v.y;
        px[2 * p + 1] = v.z;  py[2 * p + 1] = v.w;
    }
    // c[i] = |p|^2 + 64  (+64 keeps d positive so uint-min == float-min);
    // becomes 1e30 once the point is used.
    #pragma unroll
    for (int i = 0; i < 8; i++)
        s_c[10 * lane + i] = fmaf(px[i], px[i], fmaf(py[i], py[i], 64.0f));

    __syncwarp();

    const float4* st4r = (const float4*)s_tgt;  // two targets per float4
    float acc = 0.0f;   // uniform across lanes

    #pragma unroll 2
    for (int jj = 0; jj < NPTS / 2; jj++) {
        float4 t01 = st4r[jj];                   // t0=(x,y), t1=(z,w)
        float ax = -2.0f * t01.x, ay = -2.0f * t01.y;
        float bx = -2.0f * t01.z, by = -2.0f * t01.w;

        // c loaded once, shared by both targets.
        float c[8];
        #pragma unroll
        for (int p = 0; p < 4; p++) {
            float2 cc = *(const float2*)&s_c[10 * lane + 2 * p];
            c[2 * p] = cc.x;  c[2 * p + 1] = cc.y;
        }

        // d = |t-p|^2 - |t|^2 + 64 > 0  (2 FMA per point per target)
        unsigned k0[8], k1[8];
        #pragma unroll
        for (int i = 0; i < 8; i++) {
            unsigned kk = 8u * (unsigned)lane + (unsigned)i;
            float d0 = fmaf(ax, px[i], fmaf(ay, py[i], c[i]));
            float d1 = fmaf(bx, px[i], fmaf(by, py[i], c[i]));
            k0[i] = (__float_as_uint(d0) & 0xFFFFFF00u) | kk;
            k1[i] = (__float_as_uint(d1) & 0xFFFFFF00u) | kk;
        }

        // Two independent IMNMX trees + two REDUXes (latencies overlap).
        unsigned l0 = min(min(min(k0[0], k0[1]), min(k0[2], k0[3])),
                          min(min(k0[4], k0[5]), min(k0[6], k0[7])));
        unsigned l1 = min(min(min(k1[0], k1[1]), min(k1[2], k1[3])),
                          min(min(k1[4], k1[5]), min(k1[6], k1[7])));
        unsigned kw0 = __reduce_min_sync(0xFFFFFFFFu, l0);
        unsigned kw1 = __reduce_min_sync(0xFFFFFFFFu, l1);

        // Kill target0's winner.
        unsigned p0 = kw0 & 0xFFu;
        if ((p0 >> 3) == (unsigned)lane)
            s_c[10 * lane + (p0 & 7u)] = 1e30f;

        // Rare warp-uniform fallback: target1 wanted target0's point.
        // (Removing a non-winning element never changes a min, so otherwise
        //  kw1 is already the correct post-kill argmin.)
        if (((kw0 ^ kw1) & 0xFFu) == 0u) {
            if ((p0 >> 3) == (unsigned)lane) {
                #pragma unroll
                for (int i = 0; i < 8; i++)
                    if ((p0 & 7u) == (unsigned)i) k1[i] = 0xFFFFFFFFu;
            }
            l1 = min(min(min(k1[0], k1[1]), min(k1[2], k1[3])),
                     min(min(k1[4], k1[5]), min(k1[6], k1[7])));
            kw1 = __reduce_min_sync(0xFFFFFFFFu, l1);
        }

        // Kill target1's winner.
        unsigned p1 = kw1 & 0xFFu;
        if ((p1 >> 3) == (unsigned)lane)
            s_c[10 * lane + (p1 & 7u)] = 1e30f;

        // Uniform accumulate: truncated d + half-quantum de-bias (2^(e-16)).
        float dec0 = __uint_as_float(kw0 & 0xFFFFFF00u);
        float hq0  = __uint_as_float(kw0 & 0x7F800000u) * (1.0f / 65536.0f);
        float dec1 = __uint_as_float(kw1 & 0xFFFFFF00u);
        float hq1  = __uint_as_float(kw1 & 0x7F800000u) * (1.0f / 65536.0f);
        acc += (dec0 + hq0) + (dec1 + hq1);

        __syncwarp();   // make kills visible before next iteration's c load
    }

    // Sum of |t|^2 over the batch (warp butterfly, off critical path).
    #pragma unroll
    for (int off = 16; off; off >>= 1)
        tts += __shfl_xor_sync(0xffffffffu, tts, off);

    // se_j = d_j - 64 + |t_j|^2  =>  batch sum = acc + tts - 64*256
    if (lane == 0) g_partial[b] = acc + tts - 64.0f * NPTS;
    __threadfence();

    // Fused deterministic final reduction (last block, fixed order, fp64).
    int last = 0;
    if (lane == 0) last = (atomicAdd(&g_ctr, 1) == B_TOTAL - 1);
    last = __shfl_sync(0xffffffffu, last, 0);
    if (last) {
        __threadfence();
        double s = 0.0;
        #pragma unroll
        for (int i = 0; i < B_TOTAL / 32; i++)
            s += (double)g_partial[lane + 32 * i];
        #pragma unroll
        for (int off = 16; off; off >>= 1)
            s += __shfl_xor_sync(0xffffffffu, s, off);
        if (lane == 0) {
            out[0] = (float)(s / (double)B_TOTAL / (double)(2 * NPTS));
            g_ctr = 0;                  // reset for next graph replay
        }
    }
}

extern "C" void kernel_launch(void* const* d_in, const int* in_sizes, int n_in,
                              void* d_out, int out_size) {
    const float* inp = (const float*)d_in[0];   // "input"
    const float* tgt = (const float*)d_in[1];   // "targets"
    match_kernel<<<B_TOTAL, 32>>>(inp, tgt, (float*)d_out);
}